// round 3
// baseline (speedup 1.0000x reference)
#include <cuda_runtime.h>
#include <math.h>

// ArcFace loss, fully fused single kernel.
//   loss_row = log( sum_c exp(S*clamp(pred)) - exp(S*tgt_cos) + exp(S*tgt_m) ) - S*tgt_m
//   out = mean(loss_row)
// No max-subtraction needed: S*clamp(x) in [-30,30] -> exp in [1e-13,1e13],
// row sum <= 3.2e17, safely inside fp32 range.

#define S_SCALE   30.0f
// cos(0.5), sin(0.5)
#define COS_M     0.8775825618903728f
#define SIN_M     0.479425538604203f
// sin(pi-M)*M = sin(M)*M
#define MM_CONST  (0.479425538604203f * 0.5f)
// cos(pi-M) = -cos(M)
#define THRESH    (-0.8775825618903728f)

#define MAX_ROWS 16384
__device__ float        g_row_loss[MAX_ROWS];
__device__ unsigned int g_done_count;   // zero-initialized; last block resets to 0

__device__ __forceinline__ float clamp1(float x) {
    return fminf(1.0f, fmaxf(-1.0f, x));
}

__global__ void __launch_bounds__(256)
arcface_fused_kernel(const float* __restrict__ pred,
                     const void* __restrict__ target,
                     float* __restrict__ out,
                     int C, int n)
{
    const int row  = blockIdx.x;
    const int tid  = threadIdx.x;
    const int lane = tid & 31;
    const int wid  = tid >> 5;

    const float* rowp = pred + (size_t)row * (size_t)C;

    // ---- Block-local target-dtype detection (warp 0 only) + early target load.
    // Interpreted as int32 words, odd indices are either int64 high words
    // (all zero, targets < 32000) or actual int32 targets (OR != 0 w.p. ~1).
    // These 32 words are L2-resident after the first wave.
    long long t = 0;
    float tc = 0.0f;
    if (wid == 0) {
        const int* w32 = (const int*)target;
        int probe = (2 * lane + 1 < n) ? w32[2 * lane + 1] : 0;
        int any = __reduce_or_sync(0xFFFFFFFFu, probe);
        if (lane == 0) {
            if (any == 0)  t = ((const long long*)target)[row];
            else           t = (long long)w32[row];
            tc = rowp[t];               // issue dependent load early;
        }                               // consumed only after the main loop.
    }

    // ---- Streaming sum of exp(S*clamp(x)) over the row (float4 loads).
    const float4* p4  = reinterpret_cast<const float4*>(rowp);
    const int nvec = C >> 2;            // C divisible by 4 (32000)
    float acc = 0.0f;
    #pragma unroll 4
    for (int i = tid; i < nvec; i += blockDim.x) {
        float4 v = p4[i];
        acc += __expf(S_SCALE * clamp1(v.x));
        acc += __expf(S_SCALE * clamp1(v.y));
        acc += __expf(S_SCALE * clamp1(v.z));
        acc += __expf(S_SCALE * clamp1(v.w));
    }
    for (int i = (nvec << 2) + tid; i < C; i += blockDim.x)
        acc += __expf(S_SCALE * clamp1(rowp[i]));

    // ---- Block reduction.
    __shared__ float warp_sums[8];
    #pragma unroll
    for (int off = 16; off > 0; off >>= 1)
        acc += __shfl_xor_sync(0xFFFFFFFFu, acc, off);
    if (lane == 0) warp_sums[wid] = acc;
    __syncthreads();

    __shared__ bool s_is_last;
    if (tid == 0) {
        float total = 0.0f;
        #pragma unroll
        for (int w = 0; w < 8; w++) total += warp_sums[w];

        float tcc = clamp1(tc);
        // cos(acos(t)+M) = t*cosM - sqrt(1-t^2)*sinM
        float tm_hard = tcc * COS_M - sqrtf(fmaxf(0.0f, 1.0f - tcc * tcc)) * SIN_M;
        float tm = (tcc > THRESH) ? tm_hard : (tcc - MM_CONST);
        float sum = total - __expf(S_SCALE * tcc) + __expf(S_SCALE * tm);
        g_row_loss[row] = logf(sum) - S_SCALE * tm;

        __threadfence();                              // publish row loss
        unsigned int prev = atomicAdd(&g_done_count, 1u);
        s_is_last = (prev == (unsigned int)(gridDim.x - 1));
    }
    __syncthreads();

    // ---- Last block computes the mean (deterministic fixed-shape reduction).
    if (s_is_last) {
        __threadfence();                              // acquire all row losses
        __shared__ double dwarp[8];
        double d = 0.0;
        for (int i = tid; i < n; i += blockDim.x)
            d += (double)g_row_loss[i];
        #pragma unroll
        for (int off = 16; off > 0; off >>= 1)
            d += __shfl_xor_sync(0xFFFFFFFFu, d, off);
        if (lane == 0) dwarp[wid] = d;
        __syncthreads();
        if (tid == 0) {
            double tot = 0.0;
            #pragma unroll
            for (int w = 0; w < 8; w++) tot += dwarp[w];
            out[0] = (float)(tot / (double)n);
            g_done_count = 0;                         // reset for next graph replay
        }
    }
}

extern "C" void kernel_launch(void* const* d_in, const int* in_sizes, int n_in,
                              void* d_out, int out_size)
{
    const float* pred   = (const float*)d_in[0];
    const void*  target = d_in[1];
    float*       out    = (float*)d_out;

    const int n = in_sizes[1];              // number of rows (targets)
    const int C = in_sizes[0] / n;          // classes per row

    arcface_fused_kernel<<<n, 256>>>(pred, target, out, C, n);
}

// round 4
// speedup vs baseline: 1.1584x; 1.1584x over previous
#include <cuda_runtime.h>
#include <math.h>

// ArcFace loss, two-kernel streaming formulation.
//   loss_row = log( sum_c exp(S*clamp(pred)) - exp(S*tgt_cos) + exp(S*tgt_m) ) - S*tgt_m
//   out = mean(loss_row)
// No max-subtraction needed: S*clamp(x) in [-30,30] -> exp in [1e-13,1e13],
// row sum <= 3.2e17, safely inside fp32 range.
//
// exp(S*clamp(x,-1,1)) == ex2( clamp(x*K, -K, K) ) with K = S*log2(e).

#define K_S_LOG2E 43.2808512266689f   // 30 * log2(e)
// cos(0.5), sin(0.5)
#define COS_M     0.8775825618903728f
#define SIN_M     0.479425538604203f
// sin(pi-M)*M = sin(M)*M
#define MM_CONST  (0.479425538604203f * 0.5f)
// cos(pi-M) = -cos(M)
#define THRESH    (-0.8775825618903728f)

#define MAX_ROWS 16384
__device__ float g_row_loss[MAX_ROWS];

// ex2.approx of clamp(x*K, -K, K): 4 instructions (FMUL-imm, 2x FMNMX, MUFU.EX2)
__device__ __forceinline__ float expS(float x) {
    float y = fminf(K_S_LOG2E, fmaxf(-K_S_LOG2E, x * K_S_LOG2E));
    float r;
    asm("ex2.approx.f32 %0, %1;" : "=f"(r) : "f"(y));
    return r;
}

__device__ __forceinline__ float clamp1(float x) {
    return fminf(1.0f, fmaxf(-1.0f, x));
}

__global__ void __launch_bounds__(256)
arcface_row_kernel(const float* __restrict__ pred,
                   const void* __restrict__ target,
                   int C, int n)
{
    const int row  = blockIdx.x;
    const int tid  = threadIdx.x;
    const int lane = tid & 31;
    const int wid  = tid >> 5;

    const float* rowp = pred + (size_t)row * (size_t)C;

    float acc0 = 0.0f, acc1 = 0.0f;

    if (C == 32000) {
        // 8000 float4 per row; 256 threads * 31 iters = 7936, tail 64 vecs.
        // Fixed trip count -> immediate-offset LDG.128s from one base register,
        // no per-iteration IMAD/SETP, front-batched loads (high MLP).
        const float4* p = reinterpret_cast<const float4*>(rowp) + tid;
        #pragma unroll
        for (int j = 0; j < 31; j++) {
            float4 v = p[j * 256];
            acc0 += expS(v.x);
            acc1 += expS(v.y);
            acc0 += expS(v.z);
            acc1 += expS(v.w);
        }
        if (tid < 64) {
            float4 v = p[31 * 256];
            acc0 += expS(v.x);
            acc1 += expS(v.y);
            acc0 += expS(v.z);
            acc1 += expS(v.w);
        }
    } else {
        // Generic fallback.
        const float4* p4 = reinterpret_cast<const float4*>(rowp);
        const int nvec = C >> 2;
        for (int i = tid; i < nvec; i += blockDim.x) {
            float4 v = p4[i];
            acc0 += expS(v.x);
            acc1 += expS(v.y);
            acc0 += expS(v.z);
            acc1 += expS(v.w);
        }
        for (int i = (nvec << 2) + tid; i < C; i += blockDim.x)
            acc0 += expS(rowp[i]);
    }

    float acc = acc0 + acc1;

    // ---- Block reduction.
    __shared__ float warp_sums[8];
    #pragma unroll
    for (int off = 16; off > 0; off >>= 1)
        acc += __shfl_xor_sync(0xFFFFFFFFu, acc, off);
    if (lane == 0) warp_sums[wid] = acc;
    __syncthreads();

    // ---- Target fix-up (warp 0): dtype detect + margin, off the hot path.
    // Interpreted as int32 words, odd indices are either int64 high words
    // (all zero, targets < 32000) or actual int32 targets (OR != 0 w.p. ~1).
    if (wid == 0) {
        const int* w32 = (const int*)target;
        int probe = (2 * lane + 1 < n) ? w32[2 * lane + 1] : 0;
        int any = __reduce_or_sync(0xFFFFFFFFu, probe);
        if (lane == 0) {
            float total = 0.0f;
            #pragma unroll
            for (int w = 0; w < 8; w++) total += warp_sums[w];

            long long t = (any == 0) ? ((const long long*)target)[row]
                                     : (long long)w32[row];
            float tc = clamp1(rowp[t]);
            // cos(acos(t)+M) = t*cosM - sqrt(1-t^2)*sinM
            float tm_hard = tc * COS_M - sqrtf(fmaxf(0.0f, 1.0f - tc * tc)) * SIN_M;
            float tm = (tc > THRESH) ? tm_hard : (tc - MM_CONST);
            // Same expS as in the loop so the target term cancels cleanly.
            float sum = total - expS(tc) + expS(tm);
            g_row_loss[row] = logf(sum) - 30.0f * tm;
        }
    }
}

__global__ void __launch_bounds__(1024)
arcface_reduce_kernel(float* __restrict__ out, int n)
{
    __shared__ double warp_sums[32];
    double acc = 0.0;
    for (int i = threadIdx.x; i < n; i += blockDim.x)
        acc += (double)g_row_loss[i];
    int lane = threadIdx.x & 31;
    int wid  = threadIdx.x >> 5;
    #pragma unroll
    for (int off = 16; off > 0; off >>= 1)
        acc += __shfl_xor_sync(0xFFFFFFFFu, acc, off);
    if (lane == 0) warp_sums[wid] = acc;
    __syncthreads();
    if (wid == 0) {
        acc = (lane < (blockDim.x >> 5)) ? warp_sums[lane] : 0.0;
        #pragma unroll
        for (int off = 16; off > 0; off >>= 1)
            acc += __shfl_xor_sync(0xFFFFFFFFu, acc, off);
        if (lane == 0)
            out[0] = (float)(acc / (double)n);
    }
}

extern "C" void kernel_launch(void* const* d_in, const int* in_sizes, int n_in,
                              void* d_out, int out_size)
{
    const float* pred   = (const float*)d_in[0];
    const void*  target = d_in[1];
    float*       out    = (float*)d_out;

    const int n = in_sizes[1];              // number of rows (targets)
    const int C = in_sizes[0] / n;          // classes per row

    arcface_row_kernel<<<n, 256>>>(pred, target, C, n);
    arcface_reduce_kernel<<<1, 1024>>>(out, n);
}